// round 3
// baseline (speedup 1.0000x reference)
#include <cuda_runtime.h>
#include <cstdint>

// Shapes (fixed by setup_inputs):
//   k_cache: (B=4, H=8, D=128, 128, 64) f32 -> (BH=32, D=128, SFULL=8192)
//   v_cache: (B=4, H=8, 128, 64, D=128) f32 -> (BH=32, SFULL=8192, D=128)
//   S = 6144 (derived from out_size)
// out = stack([transpose_k(:, :, :S), v(:, :S, :)]) -> (2, BH, S, D)

#define BH_    32
#define D_     128
#define SFULL_ 8192

// Fused kernel, 32 KB of output per block.
// Even blocks: K-transpose tile (d=128 x s=64): 256 B read per k-row,
//   32 KB contiguous output. Odd blocks: V copy of 2048 float4 (32 KB).
// Tiles per (b,h) identical for both halves (S/64), so the flat id
// decomposes the same way for either type.
__global__ __launch_bounds__(256) void fused_kv_kernel(
    const float*  __restrict__ kin,
    const float4* __restrict__ vin,
    float*        __restrict__ outk,
    float4*       __restrict__ outv,
    int S, int tilesPerBh)
{
    const int b  = blockIdx.x;
    const int t  = threadIdx.x;
    const int id = b >> 1;
    const int bh = id / tilesPerBh;
    const int jj = id - bh * tilesPerBh;

    if (b & 1) {
        // ---------------- V copy: contiguous 32 KB chunk --------------------
        const float4* src = vin  + (size_t)bh * (SFULL_ * (D_ / 4)) + (size_t)jj * 2048;
        float4*       dst = outv + (size_t)bh * ((size_t)S * (D_ / 4)) + (size_t)jj * 2048;
#pragma unroll
        for (int i = 0; i < 8; ++i)
            __stcs(dst + t + i * 256, __ldcs(src + t + i * 256));
    } else {
        // -------------- K transpose: (D=128, s=64) -> (s=64, D=128) ---------
        // tile[s][d], row stride 129 floats:
        //   STS bank = (4f+k+d) mod 32 -> all 32 banks hit once per warp
        //   LDS bank = (s+d)    mod 32 -> conflict-free (d spans 32 lanes)
        __shared__ float tile[64][129];

        const int s0 = jj * 64;
        const float* src = kin  + (size_t)bh * D_ * SFULL_ + s0;
        float*       dst = outk + (size_t)bh * (size_t)S * D_ + (size_t)s0 * D_;

        // Load: 2048 float4 in 8 iters. f-halves split across iters so each
        // warp spans f in [0,8) (or [8,16)) -> conflict-free STS, and each
        // 8-lane group reads a contiguous 128 B of one d-row.
#pragma unroll
        for (int i = 0; i < 8; ++i) {
            const int idx  = t + i * 256;          // 0..2047
            const int half = idx >> 10;            // 0 or 1
            const int r    = idx & 1023;
            const int d    = r >> 3;               // 0..127
            const int f    = (r & 7) + (half << 3);// 0..15
            float4 val = __ldcs((const float4*)(src + (size_t)d * SFULL_ + 4 * f));
            tile[4 * f + 0][d] = val.x;
            tile[4 * f + 1][d] = val.y;
            tile[4 * f + 2][d] = val.z;
            tile[4 * f + 3][d] = val.w;
        }
        __syncthreads();

        // Store: 8192 scalars; each warp writes a contiguous 128 B segment,
        // block writes a fully contiguous 32 KB output region.
#pragma unroll
        for (int i = 0; i < 32; ++i) {
            const int e = t + i * 256;
            const int s = e >> 7;                  // 0..63
            const int d = e & 127;                 // 0..127
            __stcs(dst + (size_t)s * D_ + d, tile[s][d]);
        }
    }
}

extern "C" void kernel_launch(void* const* d_in, const int* in_sizes, int n_in,
                              void* d_out, int out_size) {
    const float* k_cache = (const float*)d_in[0];
    const float* v_cache = (const float*)d_in[1];
    // seq_len is fully determined by out_size: out = 2 * BH * S * D elems.
    const int S = out_size / (2 * BH_ * D_);        // 6144
    const int tilesPerBh = S / 64;                  // 96

    float*  out_k = (float*)d_out;                                  // (BH,S,D)
    float4* out_v = (float4*)((float*)d_out + (size_t)BH_ * S * D_);

    dim3 block(256, 1, 1);
    dim3 grid((unsigned)(2 * BH_ * tilesPerBh), 1, 1);              // 6144
    fused_kv_kernel<<<grid, block>>>(k_cache, (const float4*)v_cache,
                                     out_k, out_v, S, tilesPerBh);
}

// round 4
// speedup vs baseline: 1.2128x; 1.2128x over previous
#include <cuda_runtime.h>
#include <cstdint>

// Shapes (fixed by setup_inputs):
//   k_cache: (B=4, H=8, D=128, 128, 64) f32 -> (BH=32, D=128, SFULL=8192)
//   v_cache: (B=4, H=8, 128, 64, D=128) f32 -> (BH=32, SFULL=8192, D=128)
//   S = 6144 (derived from out_size)
// out = stack([transpose_k(:, :, :S), v(:, :S, :)]) -> (2, BH, S, D)

#define BH_    32
#define D_     128
#define SFULL_ 8192

// Fused kernel (R2 structure, proven 78.4% DRAM):
//   Even blocks: K-transpose tile (d=128 x s=32) -> 16 KB contiguous output.
//   Odd blocks:  V copy of 1024 float4 (16 KB), 4-deep batched MLP.
// 17 KB smem + <=32 regs -> 8 CTAs/SM (2048 threads, thread-capped).
__global__ __launch_bounds__(256, 8) void fused_kv_kernel(
    const float*  __restrict__ kin,
    const float4* __restrict__ vin,
    float*        __restrict__ outk,
    float4*       __restrict__ outv,
    int S, int tilesPerBh)
{
    const int b  = blockIdx.x;
    const int t  = threadIdx.x;
    const int id = b >> 1;
    const int bh = id / tilesPerBh;
    const int jj = id - bh * tilesPerBh;

    if (b & 1) {
        // ---------------- V copy: contiguous 16 KB chunk --------------------
        const float4* src = vin  + (size_t)bh * (SFULL_ * (D_ / 4)) + (size_t)jj * 1024;
        float4*       dst = outv + (size_t)bh * ((size_t)S * (D_ / 4)) + (size_t)jj * 1024;

        // Batch all 4 loads before any store: guaranteed 4-deep MLP.
        float4 v0 = src[t];
        float4 v1 = src[t + 256];
        float4 v2 = src[t + 512];
        float4 v3 = src[t + 768];
        dst[t]       = v0;
        dst[t + 256] = v1;
        dst[t + 512] = v2;
        dst[t + 768] = v3;
    } else {
        // -------------- K transpose: (D=128, s=32) -> (s=32, D=128) ---------
        // tile[s][d], row stride 129 floats:
        //   STS bank = (4f+k+d) mod 32 -> all 32 banks hit exactly once/warp
        //   LDS bank = (s+d)    mod 32 -> conflict-free
        __shared__ float tile[32][129];

        const int s0 = jj * 32;
        const float* src = kin  + (size_t)bh * D_ * SFULL_ + s0;
        float*       dst = outk + (size_t)bh * (size_t)S * D_ + (size_t)s0 * D_;

        // Load: 1024 float4; batch all 4 LDGs up front (4-deep MLP), then
        // scatter to smem. Each 8-lane group reads contiguous 128 B of a row.
        float4 r[4];
#pragma unroll
        for (int i = 0; i < 4; ++i) {
            const int idx = t + i * 256;
            const int d = idx >> 3;       // 0..127
            const int f = idx & 7;        // float4 index along s
            r[i] = *(const float4*)(src + (size_t)d * SFULL_ + 4 * f);
        }
#pragma unroll
        for (int i = 0; i < 4; ++i) {
            const int idx = t + i * 256;
            const int d = idx >> 3;
            const int f = idx & 7;
            tile[4 * f + 0][d] = r[i].x;
            tile[4 * f + 1][d] = r[i].y;
            tile[4 * f + 2][d] = r[i].z;
            tile[4 * f + 3][d] = r[i].w;
        }
        __syncthreads();

        // Store: 4096 scalars; each warp writes a contiguous 128 B segment,
        // block writes a fully contiguous 16 KB output region.
#pragma unroll
        for (int i = 0; i < 16; ++i) {
            const int e = t + i * 256;
            const int s = e >> 7;         // 0..31
            const int d = e & 127;        // 0..127
            dst[(size_t)s * D_ + d] = tile[s][d];
        }
    }
}

extern "C" void kernel_launch(void* const* d_in, const int* in_sizes, int n_in,
                              void* d_out, int out_size) {
    const float* k_cache = (const float*)d_in[0];
    const float* v_cache = (const float*)d_in[1];
    // seq_len is fully determined by out_size: out = 2 * BH * S * D elems.
    const int S = out_size / (2 * BH_ * D_);        // 6144
    const int tilesPerBh = S / 32;                  // 192

    float*  out_k = (float*)d_out;                                  // (BH,S,D)
    float4* out_v = (float4*)((float*)d_out + (size_t)BH_ * S * D_);

    dim3 block(256, 1, 1);
    dim3 grid((unsigned)(2 * BH_ * tilesPerBh), 1, 1);              // 12288
    fused_kv_kernel<<<grid, block>>>(k_cache, (const float4*)v_cache,
                                     out_k, out_v, S, tilesPerBh);
}